// round 5
// baseline (speedup 1.0000x reference)
#include <cuda_runtime.h>

#define NROWS 16384
#define HDIM  128
#define NH    (NROWS * HDIM)      // 2097152
#define NBLK1 512
#define NBLK2 512

// Scratch (no allocations allowed) — __device__ globals.
__device__ float g_xn[NROWS];               // ||x_i||^2
__device__ float g_diag[NROWS];             // dist[i,i]
__device__ float g_ys_part[NBLK1 * HDIM];   // per-block partial of sum_j y_j
__device__ float g_sy_part[NBLK1];          // per-block partial of sum_j ||y_j||^2
__device__ float g_diag_part[NBLK1];        // per-block partial of sum_i diag_i
__device__ float g_ys[HDIM];                // sum_j y_j
__device__ float g_SY;                      // sum_j ||y_j||^2
__device__ float g_nce_part[NBLK2];

__device__ __forceinline__ float wred(float v) {
#pragma unroll
    for (int o = 16; o; o >>= 1) v += __shfl_xor_sync(0xffffffffu, v, o);
    return v;
}

// K1: bi-sum + per-row stats + deterministic block partials.
// One warp per row; lane covers 4 floats (float4). Row stride in input = D*H = 256 floats = 64 float4.
__global__ void __launch_bounds__(256) k1(const float4* __restrict__ enc,
                                          const float4* __restrict__ dec,
                                          float* __restrict__ out) {
    const int warp = threadIdx.x >> 5, lane = threadIdx.x & 31;
    float4* out4 = (float4*)out;

    float4 ys_acc = make_float4(0.f, 0.f, 0.f, 0.f);
    float sy_acc = 0.f, dg_acc = 0.f;

    for (int row = blockIdx.x * 8 + warp; row < NROWS; row += gridDim.x * 8) {
        const float4 e0 = enc[row * 64 + lane];
        const float4 e1 = enc[row * 64 + 32 + lane];
        float4 x = make_float4(e0.x + e1.x, e0.y + e1.y, e0.z + e1.z, e0.w + e1.w);
        const float4 d0 = dec[row * 64 + lane];
        const float4 d1 = dec[row * 64 + 32 + lane];
        float4 y = make_float4(d0.x + d1.x, d0.y + d1.y, d0.z + d1.z, d0.w + d1.w);

        out4[row * 32 + lane]                 = x;  // bi_enc (output 0)
        out4[(NH >> 2) + row * 32 + lane]     = x;  // bi_enc (output 1)
        out4[2 * (NH >> 2) + row * 32 + lane] = y;  // bi_dec (output 2)

        float xn = x.x * x.x + x.y * x.y + x.z * x.z + x.w * x.w;
        float yn = y.x * y.x + y.y * y.y + y.z * y.z + y.w * y.w;
        float dd = x.x * y.x + x.y * y.y + x.z * y.z + x.w * y.w;
        xn = wred(xn); yn = wred(yn); dd = wred(dd);

        ys_acc.x += y.x; ys_acc.y += y.y; ys_acc.z += y.z; ys_acc.w += y.w;

        if (lane == 0) {
            g_xn[row] = xn;
            float dg = xn + yn - 2.f * dd;
            g_diag[row] = dg;
            sy_acc += yn;
            dg_acc += dg;
        }
    }

    __shared__ float4 s_ys[8][32];
    __shared__ float s_sy[8], s_dg[8];
    s_ys[warp][lane] = ys_acc;
    if (lane == 0) { s_sy[warp] = sy_acc; s_dg[warp] = dg_acc; }
    __syncthreads();

    if (threadIdx.x < 32) {
        float4 a = s_ys[0][threadIdx.x];
#pragma unroll
        for (int w = 1; w < 8; w++) {
            float4 v = s_ys[w][threadIdx.x];
            a.x += v.x; a.y += v.y; a.z += v.z; a.w += v.w;
        }
        ((float4*)g_ys_part)[blockIdx.x * 32 + threadIdx.x] = a;
    } else if (threadIdx.x == 32) {
        float s = 0.f;
#pragma unroll
        for (int w = 0; w < 8; w++) s += s_sy[w];
        g_sy_part[blockIdx.x] = s;
    } else if (threadIdx.x == 33) {
        float s = 0.f;
#pragma unroll
        for (int w = 0; w < 8; w++) s += s_dg[w];
        g_diag_part[blockIdx.x] = s;
    }
}

// K2: reduce NBLK1 partials -> g_ys, g_SY, and write diagonal_loss.
__global__ void __launch_bounds__(256) k2(float* __restrict__ out) {
    __shared__ float sh[256];
    const int t = threadIdx.x;

    { // ys columns: 2 threads per column, 256 partials each
        const int col = t & 127, half = t >> 7;
        float s = 0.f;
#pragma unroll 4
        for (int b = half * (NBLK1 / 2); b < (half + 1) * (NBLK1 / 2); b++)
            s += g_ys_part[b * HDIM + col];
        sh[t] = s;
    }
    __syncthreads();
    if (t < 128) g_ys[t] = sh[t] + sh[t + 128];
    __syncthreads();

    { // SY
        sh[t] = g_sy_part[t] + g_sy_part[t + 256];
        __syncthreads();
        for (int s = 128; s; s >>= 1) {
            if (t < s) sh[t] += sh[t + s];
            __syncthreads();
        }
        if (t == 0) g_SY = sh[0];
    }
    __syncthreads();

    { // diag sum -> diagonal_loss
        sh[t] = g_diag_part[t] + g_diag_part[t + 256];
        __syncthreads();
        for (int s = 128; s; s >>= 1) {
            if (t < s) sh[t] += sh[t + s];
            __syncthreads();
        }
        if (t == 0) out[3 * NH + 1] = -sh[0] / (float)NROWS;
    }
}

// K3: closed-form row loss + per-block nce partial.
__global__ void __launch_bounds__(256) k3(const float* __restrict__ out) {
    const int warp = threadIdx.x >> 5, lane = threadIdx.x & 31;
    const float4* x4 = (const float4*)out;  // bi_enc region
    const float4 ysl = ((const float4*)g_ys)[lane];
    const float SY = g_SY;

    float acc = 0.f;
    for (int row = blockIdx.x * 8 + warp; row < NROWS; row += gridDim.x * 8) {
        const float4 x = x4[row * 32 + lane];
        float dd = x.x * ysl.x + x.y * ysl.y + x.z * ysl.z + x.w * ysl.w;
        dd = wred(dd);
        if (lane == 0) {
            float rowsum = (float)NROWS * g_xn[row] + SY - 2.f * dd;
            float rl = 5.f - rowsum + 10.f * g_diag[row];
            acc += fmaxf(rl, 0.f);
        }
    }

    __shared__ float s_acc[8];
    if (lane == 0) s_acc[warp] = acc;
    __syncthreads();
    if (threadIdx.x == 0) {
        float s = 0.f;
#pragma unroll
        for (int w = 0; w < 8; w++) s += s_acc[w];
        g_nce_part[blockIdx.x] = s;
    }
}

// K4: reduce nce partials -> nce_loss.
__global__ void __launch_bounds__(256) k4(float* __restrict__ out) {
    __shared__ float sh[256];
    const int t = threadIdx.x;
    sh[t] = g_nce_part[t] + g_nce_part[t + 256];
    __syncthreads();
    for (int s = 128; s; s >>= 1) {
        if (t < s) sh[t] += sh[t + s];
        __syncthreads();
    }
    if (t == 0) out[3 * NH] = sh[0];
}

extern "C" void kernel_launch(void* const* d_in, const int* in_sizes, int n_in,
                              void* d_out, int out_size) {
    const float4* enc = (const float4*)d_in[0];
    const float4* dec = (const float4*)d_in[1];
    float* out = (float*)d_out;

    k1<<<NBLK1, 256>>>(enc, dec, out);
    k2<<<1, 256>>>(out);
    k3<<<NBLK2, 256>>>(out);
    k4<<<1, 256>>>(out);
}

// round 6
// speedup vs baseline: 1.1283x; 1.1283x over previous
#include <cuda_runtime.h>

#define NROWS 16384
#define HDIM  128
#define NH    (NROWS * HDIM)        // 2097152
#define NBLK  148                   // 1 block per SM -> all co-resident (spin barrier safe)
#define WPB   8
#define NWARPS (NBLK * WPB)         // 1184
#define ITERS 14                    // ceil(16384 / 1184)

// Scratch (no allocations allowed) — __device__ globals.
__device__ float g_xn[NROWS];               // ||x_i||^2
__device__ float g_diag[NROWS];             // dist[i,i]
__device__ float g_ys_part[NBLK * HDIM];    // per-block partial of sum_j y_j
__device__ float g_sy_part[NBLK];           // per-block partial of sum_j ||y_j||^2
__device__ float g_dg_part[NBLK];           // per-block partial of sum_i diag_i
__device__ float g_ys[HDIM];                // sum_j y_j
__device__ float g_SY;                      // sum_j ||y_j||^2
__device__ float g_nce_part[NBLK];
// Grid-barrier state. Counters are reset by the releasing block each launch so
// the kernel is graph-replay safe; g_gen monotonically increases (wraps fine).
__device__ unsigned g_c1 = 0, g_c2 = 0, g_gen = 0;

__device__ __forceinline__ float wred(float v) {
#pragma unroll
    for (int o = 16; o; o >>= 1) v += __shfl_xor_sync(0xffffffffu, v, o);
    return v;
}

__global__ void __launch_bounds__(256, 1)
fused(const float4* __restrict__ enc, const float4* __restrict__ dec,
      float* __restrict__ out) {
    const int warp = threadIdx.x >> 5, lane = threadIdx.x & 31;
    const int gwarp = blockIdx.x * WPB + warp;
    float4* out4 = (float4*)out;

    __shared__ float4 s_ys[WPB][32];
    __shared__ float   s_sy[WPB], s_dg[WPB], s_acc[WPB];
    __shared__ float   s_red[256];
    __shared__ unsigned s_flag;

    unsigned start_gen = 0;
    if (threadIdx.x == 0) start_gen = *(volatile unsigned*)&g_gen;

    // ---------------- Phase 1: bi-sum, outputs, per-row stats, block partials
    float4 xr[ITERS];
    float4 ys_acc = make_float4(0.f, 0.f, 0.f, 0.f);
    float sy_acc = 0.f, dg_acc = 0.f;

#pragma unroll
    for (int it = 0; it < ITERS; it++) {
        const int row = gwarp + it * NWARPS;
        xr[it] = make_float4(0.f, 0.f, 0.f, 0.f);
        if (row < NROWS) {
            const float4 e0 = enc[row * 64 + lane];
            const float4 e1 = enc[row * 64 + 32 + lane];
            float4 x = make_float4(e0.x + e1.x, e0.y + e1.y, e0.z + e1.z, e0.w + e1.w);
            const float4 d0 = dec[row * 64 + lane];
            const float4 d1 = dec[row * 64 + 32 + lane];
            float4 y = make_float4(d0.x + d1.x, d0.y + d1.y, d0.z + d1.z, d0.w + d1.w);

            out4[row * 32 + lane]                 = x;  // bi_enc (output 0)
            out4[(NH >> 2) + row * 32 + lane]     = x;  // bi_enc (output 1)
            out4[2 * (NH >> 2) + row * 32 + lane] = y;  // bi_dec (output 2)
            xr[it] = x;                                 // keep for phase 2

            float xn = x.x * x.x + x.y * x.y + x.z * x.z + x.w * x.w;
            float yn = y.x * y.x + y.y * y.y + y.z * y.z + y.w * y.w;
            float dd = x.x * y.x + x.y * y.y + x.z * y.z + x.w * y.w;
            xn = wred(xn); yn = wred(yn); dd = wred(dd);

            ys_acc.x += y.x; ys_acc.y += y.y; ys_acc.z += y.z; ys_acc.w += y.w;
            if (lane == 0) {
                g_xn[row] = xn;
                float dg = xn + yn - 2.f * dd;
                g_diag[row] = dg;
                sy_acc += yn;
                dg_acc += dg;
            }
        }
    }

    s_ys[warp][lane] = ys_acc;
    if (lane == 0) { s_sy[warp] = sy_acc; s_dg[warp] = dg_acc; }
    __syncthreads();

    if (threadIdx.x < 32) {
        float4 a = s_ys[0][threadIdx.x];
#pragma unroll
        for (int w = 1; w < WPB; w++) {
            float4 v = s_ys[w][threadIdx.x];
            a.x += v.x; a.y += v.y; a.z += v.z; a.w += v.w;
        }
        ((float4*)g_ys_part)[blockIdx.x * 32 + threadIdx.x] = a;
        __threadfence();
    } else if (threadIdx.x == 32) {
        float s = 0.f;
#pragma unroll
        for (int w = 0; w < WPB; w++) s += s_sy[w];
        g_sy_part[blockIdx.x] = s;
        __threadfence();
    } else if (threadIdx.x == 33) {
        float s = 0.f;
#pragma unroll
        for (int w = 0; w < WPB; w++) s += s_dg[w];
        g_dg_part[blockIdx.x] = s;
        __threadfence();
    }
    __syncthreads();

    // ---------------- Arrival: last block reduces the mid partials
    if (threadIdx.x == 0) s_flag = (atomicAdd(&g_c1, 1) == NBLK - 1);
    __syncthreads();

    if (s_flag) {
        // ys column reduce: 2 threads per column, 74 partial rows each (L2-hot).
        const int col = threadIdx.x & 127, half = threadIdx.x >> 7;
        float s = 0.f;
#pragma unroll 4
        for (int b = half * (NBLK / 2); b < (half + 1) * (NBLK / 2); b++)
            s += g_ys_part[b * HDIM + col];
        s_red[threadIdx.x] = s;
        __syncthreads();
        if (threadIdx.x < 128) {
            g_ys[threadIdx.x] = s_red[threadIdx.x] + s_red[threadIdx.x + 128];
            __threadfence();
        }
        __syncthreads();

        // SY reduce
        s_red[threadIdx.x] = (threadIdx.x < NBLK) ? g_sy_part[threadIdx.x] : 0.f;
        __syncthreads();
        for (int st = 128; st; st >>= 1) {
            if (threadIdx.x < st) s_red[threadIdx.x] += s_red[threadIdx.x + st];
            __syncthreads();
        }
        if (threadIdx.x == 0) g_SY = s_red[0];
        __syncthreads();

        // diag-sum reduce -> diagonal_loss
        s_red[threadIdx.x] = (threadIdx.x < NBLK) ? g_dg_part[threadIdx.x] : 0.f;
        __syncthreads();
        for (int st = 128; st; st >>= 1) {
            if (threadIdx.x < st) s_red[threadIdx.x] += s_red[threadIdx.x + st];
            __syncthreads();
        }
        if (threadIdx.x == 0) {
            out[3 * NH + 1] = -s_red[0] / (float)NROWS;
            g_c1 = 0;                       // reset for next graph replay
            __threadfence();
            atomicAdd(&g_gen, 1);           // release
        }
    }

    // ---------------- Spin barrier (all 148 blocks resident -> cannot deadlock)
    if (threadIdx.x == 0) {
        while (*(volatile unsigned*)&g_gen == start_gen) { }
        __threadfence();
    }
    __syncthreads();

    // ---------------- Phase 2: closed-form row loss from register-held x
    const float4 ysl = ((const float4*)g_ys)[lane];
    const float SY = g_SY;

    float acc = 0.f;
#pragma unroll
    for (int it = 0; it < ITERS; it++) {
        const int row = gwarp + it * NWARPS;
        if (row < NROWS) {
            const float4 x = xr[it];
            float dd = x.x * ysl.x + x.y * ysl.y + x.z * ysl.z + x.w * ysl.w;
            dd = wred(dd);
            if (lane == 0) {
                float rowsum = (float)NROWS * g_xn[row] + SY - 2.f * dd;
                float rl = 5.f - rowsum + 10.f * g_diag[row];
                acc += fmaxf(rl, 0.f);
            }
        }
    }

    if (lane == 0) s_acc[warp] = acc;
    __syncthreads();
    if (threadIdx.x == 0) {
        float s = 0.f;
#pragma unroll
        for (int w = 0; w < WPB; w++) s += s_acc[w];
        g_nce_part[blockIdx.x] = s;
        __threadfence();
        s_flag = (atomicAdd(&g_c2, 1) == NBLK - 1);
    }
    __syncthreads();

    if (s_flag) {
        s_red[threadIdx.x] = (threadIdx.x < NBLK) ? g_nce_part[threadIdx.x] : 0.f;
        __syncthreads();
        for (int st = 128; st; st >>= 1) {
            if (threadIdx.x < st) s_red[threadIdx.x] += s_red[threadIdx.x + st];
            __syncthreads();
        }
        if (threadIdx.x == 0) {
            out[3 * NH] = s_red[0];
            g_c2 = 0;                       // reset for next graph replay
        }
    }
}

extern "C" void kernel_launch(void* const* d_in, const int* in_sizes, int n_in,
                              void* d_out, int out_size) {
    const float4* enc = (const float4*)d_in[0];
    const float4* dec = (const float4*)d_in[1];
    float* out = (float*)d_out;

    fused<<<NBLK, 256>>>(enc, dec, out);
}